// round 15
// baseline (speedup 1.0000x reference)
#include <cuda_runtime.h>
#include <cstdint>

// ---------------------------------------------------------------------------
// LocationSensitiveAttention — single persistent cluster kernel.
// B=32, T_ENC=1024, T_DEC=512, E=U=512, FILTERS=32, KERNEL=31.
//
// Launches: k_weff (fold conv_w@w_loc), kA_persist (ALL 512 decode steps),
// kC (c = e_out @ enc).
//
// kA_persist: grid 128, block 512, cluster (4,1,1). Each cluster = one batch;
// CTA rank r owns te-slice [r*256, r*256+256). Cross-CTA communication
// (softmax sum, prev halo) is intra-cluster via DSMEM + barrier.cluster.
//
// R14->R15: SOFTWARE-PIPELINED tile loop. The R13 pipe audit showed the 4
// warps/SMSP run phase-locked: FFMA2 chain (FMA pipe) then tanh epilogue
// (MUFU rt=8) in lockstep, so the FMA pipe idles ~1K cyc/SMSP/tile during
// MUFU bursts (measured 62K cyc/step vs 31.7K FFMA2 floor). Now each loop
// body contains FMA(tile i) AND epilogue(tile i-1) in one basic block, so
// ptxas interleaves MUFU into the FFMA2 stream. enc is folded into the acc
// init (acc = query+bias+enc), removing the epilogue add2 and the long-lived
// ev[] registers. (redux.sync.add.f32 from R14 is NOT supported on sm_103 —
// back to the 5-round SHFL butterfly.)
// ---------------------------------------------------------------------------

#define BQ 32
#define TENC 1024
#define TDEC 512
#define EDIM 512
#define NFILT 32
#define KW 31
#define NUP 256              // u-pairs (EDIM/2)

typedef unsigned long long ull;

// static device scratch (no allocation)
__device__ ull g_W2[KW * NUP];   // Weff packed f32x2 [k][upair]
__device__ ull g_cb2[NUP];       // conv_b @ w_loc packed

// ---- dynamic smem layout for kA_persist -----------------------------------
#define SM_W2    0                       // 31*256*8  = 63488
#define SM_P2S   63488                   // 288*8     = 2304
#define SM_PREV  65792                   // 256*4     = 1024
#define SM_PART  66816                   // 8*256*4   = 8192
#define SM_EXS   75008                   // 256*4     = 1024
#define SM_RED   76032                   // 16*4      = 64
#define SM_SSUM  76096                   // 4
#define SM_INV   76100                   // 4
#define SMEM_BYTES 76160

// ---- f32x2 helpers --------------------------------------------------------
__device__ __forceinline__ ull fma2(ull a, ull b, ull c) {
    ull d;
    asm("fma.rn.f32x2 %0, %1, %2, %3;" : "=l"(d) : "l"(a), "l"(b), "l"(c));
    return d;
}
__device__ __forceinline__ ull add2(ull a, ull b) {
    ull d;
    asm("add.rn.f32x2 %0, %1, %2;" : "=l"(d) : "l"(a), "l"(b));
    return d;
}
__device__ __forceinline__ ull pack2(float lo, float hi) {
    ull d;
    asm("mov.b64 %0, {%1, %2};" : "=l"(d) : "f"(lo), "f"(hi));
    return d;
}
__device__ __forceinline__ void unpack2(ull v, float& lo, float& hi) {
    asm("mov.b64 {%0, %1}, %2;" : "=f"(lo), "=f"(hi) : "l"(v));
}
// tanh(x) = 1 - 2/(1+exp(2x)); ex2+rcp approx (~1e-6), saturates correctly.
__device__ __forceinline__ float fast_tanh(float x) {
    float m = x * 2.8853900817779268f;    // 2*log2(e)
    float t, r;
    asm("ex2.approx.f32 %0, %1;" : "=f"(t) : "f"(m));
    float d = 1.0f + t;
    asm("rcp.approx.f32 %0, %1;" : "=f"(r) : "f"(d));
    return fmaf(-2.0f, r, 1.0f);
}
// ---- cluster helpers ------------------------------------------------------
__device__ __forceinline__ uint32_t smem_u32(const void* p) {
    uint32_t a;
    asm("{ .reg .u64 t; cvta.to.shared.u64 t, %1; cvt.u32.u64 %0, t; }"
        : "=r"(a) : "l"(p));
    return a;
}
__device__ __forceinline__ float dsmem_ldf(uint32_t laddr, int rank) {
    uint32_t ra;
    asm("mapa.shared::cluster.u32 %0, %1, %2;" : "=r"(ra) : "r"(laddr), "r"(rank));
    float v;
    asm volatile("ld.shared::cluster.f32 %0, [%1];" : "=f"(v) : "r"(ra));
    return v;
}
__device__ __forceinline__ void cluster_sync_all() {
    asm volatile("barrier.cluster.arrive.aligned;" ::: "memory");
    asm volatile("barrier.cluster.wait.aligned;" ::: "memory");
}

// ---- weight folding -------------------------------------------------------
__global__ void k_weff(const float* __restrict__ cw, const float* __restrict__ cb,
                       const float* __restrict__ wl) {
    int idx = blockIdx.x * blockDim.x + threadIdx.x;
    if (idx < KW * NUP) {
        int k = idx / NUP, up = idx % NUP;
        float slo = 0.0f, shi = 0.0f;
        #pragma unroll
        for (int f = 0; f < NFILT; ++f) {
            float w = cw[k * NFILT + f];
            slo += w * wl[f * EDIM + 2 * up];
            shi += w * wl[f * EDIM + 2 * up + 1];
        }
        g_W2[idx] = pack2(slo, shi);
    }
    if (idx < NUP) {
        float slo = 0.0f, shi = 0.0f;
        #pragma unroll
        for (int f = 0; f < NFILT; ++f) {
            float w = cb[f];
            slo += w * wl[f * EDIM + 2 * idx];
            shi += w * wl[f * EDIM + 2 * idx + 1];
        }
        g_cb2[idx] = pack2(slo, shi);
    }
}

// FMA chain for one 8-te tile: ACC must be pre-initialized (qb2 + enc).
#define TILE_FMA(ACC, TE_L)                                                  \
    do {                                                                     \
        ull r_[8];                                                           \
        _Pragma("unroll")                                                    \
        for (int j_ = 0; j_ < 8; ++j_) r_[j_] = p2s[(TE_L) + j_];            \
        _Pragma("unroll")                                                    \
        for (int k_ = 0; k_ < KW; ++k_) {                                    \
            ull wk_ = w2s[k_ * NUP + upair];                                 \
            _Pragma("unroll")                                                \
            for (int j_ = 0; j_ < 8; ++j_)                                   \
                ACC[j_] = fma2(r_[(k_ + j_) & 7], wk_, ACC[j_]);             \
            if (k_ < KW - 1) r_[k_ & 7] = p2s[(TE_L) + k_ + 8];              \
        }                                                                    \
    } while (0)

// epilogue for one finished tile: tanh, v_a dot, warp reduce, part_s write.
#define TILE_EPI(ACC, TE_L)                                                  \
    do {                                                                     \
        _Pragma("unroll")                                                    \
        for (int j_ = 0; j_ < 8; ++j_) {                                     \
            float xlo_, xhi_;                                                \
            unpack2(ACC[j_], xlo_, xhi_);                                    \
            float pj_ = fmaf(va_hi, fast_tanh(xhi_), va_lo * fast_tanh(xlo_));\
            _Pragma("unroll")                                                \
            for (int m_ = 16; m_ >= 1; m_ >>= 1)                             \
                pj_ += __shfl_xor_sync(0xffffffffu, pj_, m_);                \
            if (lane == 0) part_s[wu * 256 + (TE_L) + j_] = pj_;             \
        }                                                                    \
    } while (0)

// ---- the whole scan in one kernel ----------------------------------------
__global__ void __launch_bounds__(512, 1) __cluster_dims__(4, 1, 1)
kA_persist(const float* __restrict__ enc, const float* __restrict__ dec,
           const float* __restrict__ va, const float* __restrict__ ba,
           float* __restrict__ out) {
    extern __shared__ char smem_raw[];
    ull*   w2s     = reinterpret_cast<ull*>(smem_raw + SM_W2);
    ull*   p2s     = reinterpret_cast<ull*>(smem_raw + SM_P2S);
    float* prev_s  = reinterpret_cast<float*>(smem_raw + SM_PREV);
    float* part_s  = reinterpret_cast<float*>(smem_raw + SM_PART);
    float* exs_s   = reinterpret_cast<float*>(smem_raw + SM_EXS);
    float* red_s   = reinterpret_cast<float*>(smem_raw + SM_RED);
    float* ssum_p  = reinterpret_cast<float*>(smem_raw + SM_SSUM);
    float* inv_p   = reinterpret_cast<float*>(smem_raw + SM_INV);

    const int bx = blockIdx.x;
    const int b = bx >> 2;
    const int rank = bx & 3;            // cluster ctarank (1-D cluster of 4)
    const int te0 = rank * 256;

    const int tid = threadIdx.x;
    const int lane = tid & 31;
    const int warp = tid >> 5;
    const int wu = warp & 7;            // u-group
    const int half = warp >> 3;         // te half (0..1)
    const int upair = wu * 32 + lane;   // 0..255
    const int teW = half * 128;         // warp's CTA-local te base

    const ull* enc2 = reinterpret_cast<const ull*>(enc);
    const ull* dec2 = reinterpret_cast<const ull*>(dec);
    const ull* va2  = reinterpret_cast<const ull*>(va);
    const ull* ba2  = reinterpret_cast<const ull*>(ba);
    float* e_out = out + (size_t)BQ * TDEC * EDIM;

    // stage W2 into smem (once), init state
    for (int i = tid; i < KW * NUP; i += 512) w2s[i] = g_W2[i];
    if (tid < 288) p2s[tid] = 0ull;
    if (tid < 256) prev_s[tid] = 0.0f;

    // per-thread constants
    float va_lo, va_hi;
    unpack2(__ldg(va2 + upair), va_lo, va_hi);
    const ull bias2 = add2(__ldg(ba2 + upair), g_cb2[upair]);
    const ull* enc_row = enc2 + ((size_t)b * TENC + te0 + teW) * NUP + upair;
    const ull* dec_row = dec2 + (size_t)b * TDEC * NUP + upair;
    const uint32_t prev_addr = smem_u32(prev_s);
    const uint32_t ssum_addr = smem_u32(ssum_p);
    __syncthreads();

    for (int t = 0; t < TDEC; ++t) {
        const ull qb2 = add2(__ldg(dec_row + (size_t)t * NUP), bias2);

        // ---- software-pipelined loc+tanh+reduce over 16 tiles of 8 te -----
        ull accP[8], accC[8];

        // prologue: tile 0 (acc init = query+bias+enc, then FMA chain)
        #pragma unroll
        for (int j = 0; j < 8; ++j)
            accP[j] = add2(qb2, __ldg(enc_row + (size_t)j * NUP));
        TILE_FMA(accP, teW + 0);

        #pragma unroll 1
        for (int tile = 1; tile < 16; ++tile) {
            const int te_l = teW + tile * 8;
            // current tile FMA chain...
            #pragma unroll
            for (int j = 0; j < 8; ++j)
                accC[j] = add2(qb2, __ldg(enc_row + (size_t)(tile * 8 + j) * NUP));
            TILE_FMA(accC, te_l);
            // ...interleaved (same basic block) with previous tile's epilogue
            TILE_EPI(accP, te_l - 8);
            #pragma unroll
            for (int j = 0; j < 8; ++j) accP[j] = accC[j];
        }
        TILE_EPI(accP, teW + 120);     // tail: tile 15
        __syncthreads();

        // ---- exp + slice sum (no max-sub: |e_raw| <= sum|v_a| < 26) -------
        float ex = 0.0f;
        if (tid < 256) {
            float s = part_s[0 * 256 + tid] + part_s[1 * 256 + tid] +
                      part_s[2 * 256 + tid] + part_s[3 * 256 + tid] +
                      part_s[4 * 256 + tid] + part_s[5 * 256 + tid] +
                      part_s[6 * 256 + tid] + part_s[7 * 256 + tid];
            ex = __expf(s);
            exs_s[tid] = ex;
        }
        float sw = ex;
        #pragma unroll
        for (int m = 16; m >= 1; m >>= 1)
            sw += __shfl_xor_sync(0xffffffffu, sw, m);
        if (lane == 0) red_s[warp] = sw;
        __syncthreads();
        if (tid == 0) {
            float tot = 0.0f;
            #pragma unroll
            for (int w = 0; w < 16; ++w) tot += red_s[w];
            *ssum_p = tot;
        }

        // ---- cluster exchange of the 4 slice sums -------------------------
        cluster_sync_all();                    // slice_sum visible cluster-wide
        if (tid == 0) {
            float s0 = dsmem_ldf(ssum_addr, 0);
            float s1 = dsmem_ldf(ssum_addr, 1);
            float s2 = dsmem_ldf(ssum_addr, 2);
            float s3 = dsmem_ldf(ssum_addr, 3);
            *inv_p = 1.0f / (s0 + s1 + s2 + s3);
        }
        __syncthreads();

        // ---- e, prev update, e_out output ---------------------------------
        if (tid < 256) {
            float e = exs_s[tid] * (*inv_p);
            __stcs(&e_out[((size_t)b * TDEC + t) * TENC + te0 + tid], e);
            prev_s[tid] += e;
        }

        // ---- rebuild window for next step (halo via DSMEM) ----------------
        cluster_sync_all();                    // all ranks' prev_s updated
        if (tid < 286) {
            int te_g = te0 - 15 + tid;
            float v = 0.0f;
            if (te_g >= 0 && te_g < TENC) {
                int r = te_g >> 8, off = te_g & 255;
                v = (r == rank) ? prev_s[off]
                                : dsmem_ldf(prev_addr + off * 4, r);
            }
            p2s[tid] = pack2(v, v);
        }
        __syncthreads();
    }
}

// ---- final context GEMM: c[b,d,:] = sum_te e[b,d,te] * enc[b,te,:] --------
__global__ void __launch_bounds__(512)
kC(const float* __restrict__ enc, float* __restrict__ out) {
    const int dtile = blockIdx.x;     // 16 tiles of 32 d-rows
    const int b = blockIdx.y;
    const int tid = threadIdx.x;
    const int upair = tid & 255;
    const int dhalf = tid >> 8;       // 0..1 -> 16 d-rows each

    const ull* enc2 = reinterpret_cast<const ull*>(enc);
    const float* e_out = out + (size_t)BQ * TDEC * EDIM;

    __shared__ float es[32][128];
    ull acc[16];
    #pragma unroll
    for (int j = 0; j < 16; ++j) acc[j] = 0ull;

    for (int c = 0; c < 8; ++c) {     // te chunks of 128
        __syncthreads();
        for (int q = tid; q < 1024; q += 512) {   // 32 rows x 32 float4
            int row = q >> 5, col4 = q & 31;
            float4 v = __ldg((const float4*)
                &e_out[((size_t)b * TDEC + dtile * 32 + row) * TENC + c * 128 + col4 * 4]);
            *(float4*)&es[row][col4 * 4] = v;
        }
        __syncthreads();

        for (int te = 0; te < 128; te += 4) {
            ull ev0 = __ldg(&enc2[((size_t)b * TENC + c * 128 + te + 0) * NUP + upair]);
            ull ev1 = __ldg(&enc2[((size_t)b * TENC + c * 128 + te + 1) * NUP + upair]);
            ull ev2 = __ldg(&enc2[((size_t)b * TENC + c * 128 + te + 2) * NUP + upair]);
            ull ev3 = __ldg(&enc2[((size_t)b * TENC + c * 128 + te + 3) * NUP + upair]);
            #pragma unroll
            for (int j = 0; j < 16; ++j) {
                float4 e4 = *(const float4*)&es[dhalf * 16 + j][te];
                acc[j] = fma2(pack2(e4.x, e4.x), ev0, acc[j]);
                acc[j] = fma2(pack2(e4.y, e4.y), ev1, acc[j]);
                acc[j] = fma2(pack2(e4.z, e4.z), ev2, acc[j]);
                acc[j] = fma2(pack2(e4.w, e4.w), ev3, acc[j]);
            }
        }
    }

    #pragma unroll
    for (int j = 0; j < 16; ++j) {
        int d = dtile * 32 + dhalf * 16 + j;
        *(ull*)&out[((size_t)b * TDEC + d) * EDIM + 2 * upair] = acc[j];
    }
}

extern "C" void kernel_launch(void* const* d_in, const int* in_sizes, int n_in,
                              void* d_out, int out_size) {
    (void)in_sizes; (void)n_in; (void)out_size;
    const float* enc = (const float*)d_in[0];
    const float* dec = (const float*)d_in[1];
    const float* cw  = (const float*)d_in[2];
    const float* cb  = (const float*)d_in[3];
    const float* wl  = (const float*)d_in[4];
    const float* va  = (const float*)d_in[5];
    const float* ba  = (const float*)d_in[6];
    float* out = (float*)d_out;

    cudaFuncSetAttribute(kA_persist,
                         cudaFuncAttributeMaxDynamicSharedMemorySize, SMEM_BYTES);

    k_weff<<<32, 256>>>(cw, cb, wl);
    kA_persist<<<BQ * 4, 512, SMEM_BYTES>>>(enc, dec, va, ba, out);
    dim3 gc(16, BQ);
    kC<<<gc, 512>>>(enc, out);
}

// round 16
// speedup vs baseline: 1.0216x; 1.0216x over previous
#include <cuda_runtime.h>
#include <cstdint>

// ---------------------------------------------------------------------------
// LocationSensitiveAttention — single persistent cluster kernel.
// B=32, T_ENC=1024, T_DEC=512, E=U=512, FILTERS=32, KERNEL=31.
//
// Launches: k_weff (fold conv_w@w_loc, pre-scale by 2*log2e), kA_persist
// (all 512 decode steps), kC (c = e_out @ enc).
//
// kA_persist: grid 128, block 512, cluster (4,1,1). Each cluster = one batch;
// CTA rank r owns te-slice [r*256, r*256+256). Cross-CTA communication
// (softmax sum, prev halo) is intra-cluster via DSMEM + barrier.cluster.
//
// R15->R16: ISSUE-COUNT reduction (tile loop was issue-slot bound: ~550
// issues/tile, only 45% FMA).
//  (a) tanh scale 2*log2e folded upstream into Weff/bias/dec, and enc's
//      scale fused via arg = fma2(ev, c2, acc) replacing the add2
//      -> the 2 FMULs/pair in the epilogue vanish.
//  (b) va folded into rcp output: va*tanh = va - 2*va*r; the constant
//      sum(va) is added ONCE per te after reduction (g_vsum).
//  (c) 5-round x 8-value SHFL butterfly (80 issues) replaced by a tree
//      multi-value reduction (3 select+shfl+add merge rounds + 2 butterfly
//      rounds = 32 issues; one predicated STS writes all 8 te sums).
// ---------------------------------------------------------------------------

#define BQ 32
#define TENC 1024
#define TDEC 512
#define EDIM 512
#define NFILT 32
#define KW 31
#define NUP 256              // u-pairs (EDIM/2)

#define CSC 2.8853900817779268f   // 2*log2(e)

typedef unsigned long long ull;

// static device scratch (no allocation)
__device__ ull   g_W2[KW * NUP];   // Weff packed f32x2 [k][upair], x CSC
__device__ ull   g_cb2[NUP];       // conv_b @ w_loc packed, x CSC
__device__ float g_vsum;           // sum over u of v_a[u]

// ---- dynamic smem layout for kA_persist -----------------------------------
#define SM_W2    0                       // 31*256*8  = 63488
#define SM_P2S   63488                   // 288*8     = 2304
#define SM_PREV  65792                   // 256*4     = 1024
#define SM_PART  66816                   // 8*256*4   = 8192
#define SM_EXS   75008                   // 256*4     = 1024
#define SM_RED   76032                   // 16*4      = 64
#define SM_SSUM  76096                   // 4
#define SM_INV   76100                   // 4
#define SMEM_BYTES 76160

// ---- f32x2 helpers --------------------------------------------------------
__device__ __forceinline__ ull fma2(ull a, ull b, ull c) {
    ull d;
    asm("fma.rn.f32x2 %0, %1, %2, %3;" : "=l"(d) : "l"(a), "l"(b), "l"(c));
    return d;
}
__device__ __forceinline__ ull add2(ull a, ull b) {
    ull d;
    asm("add.rn.f32x2 %0, %1, %2;" : "=l"(d) : "l"(a), "l"(b));
    return d;
}
__device__ __forceinline__ ull pack2(float lo, float hi) {
    ull d;
    asm("mov.b64 %0, {%1, %2};" : "=l"(d) : "f"(lo), "f"(hi));
    return d;
}
__device__ __forceinline__ void unpack2(ull v, float& lo, float& hi) {
    asm("mov.b64 {%0, %1}, %2;" : "=f"(lo), "=f"(hi) : "l"(v));
}
__device__ __forceinline__ float ex2f(float x) {
    float t;
    asm("ex2.approx.f32 %0, %1;" : "=f"(t) : "f"(x));
    return t;
}
__device__ __forceinline__ float rcpf(float x) {
    float r;
    asm("rcp.approx.f32 %0, %1;" : "=f"(r) : "f"(x));
    return r;
}
// ---- cluster helpers ------------------------------------------------------
__device__ __forceinline__ uint32_t smem_u32(const void* p) {
    uint32_t a;
    asm("{ .reg .u64 t; cvta.to.shared.u64 t, %1; cvt.u32.u64 %0, t; }"
        : "=r"(a) : "l"(p));
    return a;
}
__device__ __forceinline__ float dsmem_ldf(uint32_t laddr, int rank) {
    uint32_t ra;
    asm("mapa.shared::cluster.u32 %0, %1, %2;" : "=r"(ra) : "r"(laddr), "r"(rank));
    float v;
    asm volatile("ld.shared::cluster.f32 %0, [%1];" : "=f"(v) : "r"(ra));
    return v;
}
__device__ __forceinline__ void cluster_sync_all() {
    asm volatile("barrier.cluster.arrive.aligned;" ::: "memory");
    asm volatile("barrier.cluster.wait.aligned;" ::: "memory");
}

// ---- weight folding (pre-scaled by CSC) -----------------------------------
__global__ void k_weff(const float* __restrict__ cw, const float* __restrict__ cb,
                       const float* __restrict__ wl, const float* __restrict__ va) {
    int idx = blockIdx.x * blockDim.x + threadIdx.x;
    if (idx < KW * NUP) {
        int k = idx / NUP, up = idx % NUP;
        float slo = 0.0f, shi = 0.0f;
        #pragma unroll
        for (int f = 0; f < NFILT; ++f) {
            float w = cw[k * NFILT + f];
            slo += w * wl[f * EDIM + 2 * up];
            shi += w * wl[f * EDIM + 2 * up + 1];
        }
        g_W2[idx] = pack2(slo * CSC, shi * CSC);
    }
    if (idx < NUP) {
        float slo = 0.0f, shi = 0.0f;
        #pragma unroll
        for (int f = 0; f < NFILT; ++f) {
            float w = cb[f];
            slo += w * wl[f * EDIM + 2 * idx];
            shi += w * wl[f * EDIM + 2 * idx + 1];
        }
        g_cb2[idx] = pack2(slo * CSC, shi * CSC);
    }
    if (idx == 0) {
        float s = 0.0f;
        for (int u = 0; u < EDIM; ++u) s += va[u];
        g_vsum = s;
    }
}

// ---- the whole scan in one kernel ----------------------------------------
__global__ void __launch_bounds__(512, 1) __cluster_dims__(4, 1, 1)
kA_persist(const float* __restrict__ enc, const float* __restrict__ dec,
           const float* __restrict__ va, const float* __restrict__ ba,
           float* __restrict__ out) {
    extern __shared__ char smem_raw[];
    ull*   w2s     = reinterpret_cast<ull*>(smem_raw + SM_W2);
    ull*   p2s     = reinterpret_cast<ull*>(smem_raw + SM_P2S);
    float* prev_s  = reinterpret_cast<float*>(smem_raw + SM_PREV);
    float* part_s  = reinterpret_cast<float*>(smem_raw + SM_PART);
    float* exs_s   = reinterpret_cast<float*>(smem_raw + SM_EXS);
    float* red_s   = reinterpret_cast<float*>(smem_raw + SM_RED);
    float* ssum_p  = reinterpret_cast<float*>(smem_raw + SM_SSUM);
    float* inv_p   = reinterpret_cast<float*>(smem_raw + SM_INV);

    const int bx = blockIdx.x;
    const int b = bx >> 2;
    const int rank = bx & 3;            // cluster ctarank (1-D cluster of 4)
    const int te0 = rank * 256;

    const int tid = threadIdx.x;
    const int lane = tid & 31;
    const int warp = tid >> 5;
    const int wu = warp & 7;            // u-group
    const int half = warp >> 3;         // te half (0..1)
    const int upair = wu * 32 + lane;   // 0..255

    const ull* enc2 = reinterpret_cast<const ull*>(enc);
    const ull* dec2 = reinterpret_cast<const ull*>(dec);
    const ull* va2  = reinterpret_cast<const ull*>(va);
    const ull* ba2  = reinterpret_cast<const ull*>(ba);
    float* e_out = out + (size_t)BQ * TDEC * EDIM;

    // stage W2 into smem (once), init state
    for (int i = tid; i < KW * NUP; i += 512) w2s[i] = g_W2[i];
    if (tid < 288) p2s[tid] = 0ull;
    if (tid < 256) prev_s[tid] = 0.0f;

    // per-thread constants
    float va_lo, va_hi;
    unpack2(__ldg(va2 + upair), va_lo, va_hi);
    const float n2va_lo = -2.0f * va_lo;
    const float n2va_hi = -2.0f * va_hi;
    const ull c2 = pack2(CSC, CSC);
    // bias = (ba)*CSC + (conv_b@w_loc)*CSC   (cb2 already scaled)
    const ull bias2 = fma2(__ldg(ba2 + upair), c2, g_cb2[upair]);
    const float vsum = g_vsum;
    const ull* enc_row = enc2 + ((size_t)b * TENC + te0) * NUP + upair;
    const ull* dec_row = dec2 + (size_t)b * TDEC * NUP + upair;
    const uint32_t prev_addr = smem_u32(prev_s);
    const uint32_t ssum_addr = smem_u32(ssum_p);
    const bool b4 = (lane & 16) != 0;
    const bool b3 = (lane & 8) != 0;
    const bool b2f = (lane & 4) != 0;
    __syncthreads();

    for (int t = 0; t < TDEC; ++t) {
        // qb2 = dec*CSC + bias   (scaled query+bias, one fma2 per step)
        const ull qb2 = fma2(__ldg(dec_row + (size_t)t * NUP), c2, bias2);

        // ---- loc (Toeplitz, f32x2) + sigmoid-form tanh + reduce -----------
        #pragma unroll 1
        for (int tile = 0; tile < 16; ++tile) {
            const int te_l = half * 128 + tile * 8;

            // enc loads hoisted above the FFMA2 chain (latency covered)
            ull ev[8];
            #pragma unroll
            for (int j = 0; j < 8; ++j)
                ev[j] = __ldg(enc_row + (size_t)(te_l + j) * NUP);

            ull r[8], acc[8];
            #pragma unroll
            for (int j = 0; j < 8; ++j) { r[j] = p2s[te_l + j]; acc[j] = qb2; }
            #pragma unroll
            for (int k = 0; k < KW; ++k) {
                ull wk = w2s[k * NUP + upair];      // conflict-free LDS.64
                #pragma unroll
                for (int j = 0; j < 8; ++j)
                    acc[j] = fma2(r[(k + j) & 7], wk, acc[j]);
                if (k < KW - 1) r[k & 7] = p2s[te_l + k + 8];
            }

            // epilogue: arg = enc*CSC + acc; r = 1/(1+2^arg);
            // contribution = -2*va_lo*r_lo - 2*va_hi*r_hi  (vsum added later)
            float v[8];
            #pragma unroll
            for (int j = 0; j < 8; ++j) {
                ull arg = fma2(ev[j], c2, acc[j]);
                float ylo, yhi;
                unpack2(arg, ylo, yhi);
                float rlo = rcpf(1.0f + ex2f(ylo));
                float rhi = rcpf(1.0f + ex2f(yhi));
                v[j] = fmaf(n2va_lo, rlo, n2va_hi * rhi);
            }

            // tree multi-value reduction: 8 sums over 32 lanes.
            // merge rounds put te index into lane bits [4:2].
            #pragma unroll
            for (int j = 0; j < 4; ++j) {
                float send = b4 ? v[j] : v[j + 4];
                float keep = b4 ? v[j + 4] : v[j];
                v[j] = keep + __shfl_xor_sync(0xffffffffu, send, 16);
            }
            #pragma unroll
            for (int j = 0; j < 2; ++j) {
                float send = b3 ? v[j] : v[j + 2];
                float keep = b3 ? v[j + 2] : v[j];
                v[j] = keep + __shfl_xor_sync(0xffffffffu, send, 8);
            }
            {
                float send = b2f ? v[0] : v[1];
                float keep = b2f ? v[1] : v[0];
                float s = keep + __shfl_xor_sync(0xffffffffu, send, 4);
                s += __shfl_xor_sync(0xffffffffu, s, 2);
                s += __shfl_xor_sync(0xffffffffu, s, 1);
                if ((lane & 3) == 0)
                    part_s[wu * 256 + te_l + ((lane >> 2) & 7)] = s;
            }
        }
        __syncthreads();

        // ---- exp + slice sum (no max-sub: |e_raw| <= sum|v_a| < 26) -------
        float ex = 0.0f;
        if (tid < 256) {
            float s = part_s[0 * 256 + tid] + part_s[1 * 256 + tid] +
                      part_s[2 * 256 + tid] + part_s[3 * 256 + tid] +
                      part_s[4 * 256 + tid] + part_s[5 * 256 + tid] +
                      part_s[6 * 256 + tid] + part_s[7 * 256 + tid];
            ex = __expf(s + vsum);     // add sum(va) once per te
            exs_s[tid] = ex;
        }
        float sw = ex;
        #pragma unroll
        for (int m = 16; m >= 1; m >>= 1)
            sw += __shfl_xor_sync(0xffffffffu, sw, m);
        if (lane == 0) red_s[warp] = sw;
        __syncthreads();
        if (tid == 0) {
            float tot = 0.0f;
            #pragma unroll
            for (int w = 0; w < 16; ++w) tot += red_s[w];
            *ssum_p = tot;
        }

        // ---- cluster exchange of the 4 slice sums -------------------------
        cluster_sync_all();                    // slice_sum visible cluster-wide
        if (tid == 0) {
            float s0 = dsmem_ldf(ssum_addr, 0);
            float s1 = dsmem_ldf(ssum_addr, 1);
            float s2 = dsmem_ldf(ssum_addr, 2);
            float s3 = dsmem_ldf(ssum_addr, 3);
            *inv_p = 1.0f / (s0 + s1 + s2 + s3);
        }
        __syncthreads();

        // ---- e, prev update, e_out output ---------------------------------
        if (tid < 256) {
            float e = exs_s[tid] * (*inv_p);
            __stcs(&e_out[((size_t)b * TDEC + t) * TENC + te0 + tid], e);
            prev_s[tid] += e;
        }

        // ---- rebuild window for next step (halo via DSMEM) ----------------
        cluster_sync_all();                    // all ranks' prev_s updated
        if (tid < 286) {
            int te_g = te0 - 15 + tid;
            float v = 0.0f;
            if (te_g >= 0 && te_g < TENC) {
                int r = te_g >> 8, off = te_g & 255;
                v = (r == rank) ? prev_s[off]
                                : dsmem_ldf(prev_addr + off * 4, r);
            }
            p2s[tid] = pack2(v, v);
        }
        __syncthreads();
    }
}

// ---- final context GEMM: c[b,d,:] = sum_te e[b,d,te] * enc[b,te,:] --------
__global__ void __launch_bounds__(512)
kC(const float* __restrict__ enc, float* __restrict__ out) {
    const int dtile = blockIdx.x;     // 16 tiles of 32 d-rows
    const int b = blockIdx.y;
    const int tid = threadIdx.x;
    const int upair = tid & 255;
    const int dhalf = tid >> 8;       // 0..1 -> 16 d-rows each

    const ull* enc2 = reinterpret_cast<const ull*>(enc);
    const float* e_out = out + (size_t)BQ * TDEC * EDIM;

    __shared__ float es[32][128];
    ull acc[16];
    #pragma unroll
    for (int j = 0; j < 16; ++j) acc[j] = 0ull;

    for (int c = 0; c < 8; ++c) {     // te chunks of 128
        __syncthreads();
        for (int q = tid; q < 1024; q += 512) {   // 32 rows x 32 float4
            int row = q >> 5, col4 = q & 31;
            float4 v = __ldg((const float4*)
                &e_out[((size_t)b * TDEC + dtile * 32 + row) * TENC + c * 128 + col4 * 4]);
            *(float4*)&es[row][col4 * 4] = v;
        }
        __syncthreads();

        for (int te = 0; te < 128; te += 4) {
            ull ev0 = __ldg(&enc2[((size_t)b * TENC + c * 128 + te + 0) * NUP + upair]);
            ull ev1 = __ldg(&enc2[((size_t)b * TENC + c * 128 + te + 1) * NUP + upair]);
            ull ev2 = __ldg(&enc2[((size_t)b * TENC + c * 128 + te + 2) * NUP + upair]);
            ull ev3 = __ldg(&enc2[((size_t)b * TENC + c * 128 + te + 3) * NUP + upair]);
            #pragma unroll
            for (int j = 0; j < 16; ++j) {
                float4 e4 = *(const float4*)&es[dhalf * 16 + j][te];
                acc[j] = fma2(pack2(e4.x, e4.x), ev0, acc[j]);
                acc[j] = fma2(pack2(e4.y, e4.y), ev1, acc[j]);
                acc[j] = fma2(pack2(e4.z, e4.z), ev2, acc[j]);
                acc[j] = fma2(pack2(e4.w, e4.w), ev3, acc[j]);
            }
        }
    }

    #pragma unroll
    for (int j = 0; j < 16; ++j) {
        int d = dtile * 32 + dhalf * 16 + j;
        *(ull*)&out[((size_t)b * TDEC + d) * EDIM + 2 * upair] = acc[j];
    }
}

extern "C" void kernel_launch(void* const* d_in, const int* in_sizes, int n_in,
                              void* d_out, int out_size) {
    (void)in_sizes; (void)n_in; (void)out_size;
    const float* enc = (const float*)d_in[0];
    const float* dec = (const float*)d_in[1];
    const float* cw  = (const float*)d_in[2];
    const float* cb  = (const float*)d_in[3];
    const float* wl  = (const float*)d_in[4];
    const float* va  = (const float*)d_in[5];
    const float* ba  = (const float*)d_in[6];
    float* out = (float*)d_out;

    cudaFuncSetAttribute(kA_persist,
                         cudaFuncAttributeMaxDynamicSharedMemorySize, SMEM_BYTES);

    k_weff<<<32, 256>>>(cw, cb, wl, va);
    kA_persist<<<BQ * 4, 512, SMEM_BYTES>>>(enc, dec, va, ba, out);
    dim3 gc(16, BQ);
    kC<<<gc, 512>>>(enc, out);
}